// round 14
// baseline (speedup 1.0000x reference)
#include <cuda_runtime.h>

#define BATCH 4
#define HH 128
#define WW 128
#define CIN 64
#define CQK 8
#define NPX 8          // pixels per attn block (consecutive x)
#define PLANE (HH*WW)
#define VSTRIDE 1664   // per-pixel v region: 13 x 128-float m-pair blocks
#define ASTRIDE 28     // attn row stride (16B-aligned float4 reads)
#define APIX (25*ASTRIDE)   // 700 floats per pixel
#define ATHREADS 512

// ---------------- scratch (device globals, no runtime alloc) ----------------
__device__ float g_q[BATCH*CQK*PLANE];              //   2 MB
__device__ float g_k[BATCH*CQK*PLANE];              //   2 MB
__device__ float g_v[BATCH*CIN*PLANE];              //  16.8 MB
__device__ float g_partial[(long)BATCH*2048*3840];  // 125.8 MB fold partials

// =====================================================================
// Kernel A: 1x1-conv projections, split into 2 output-chunks per row
// grid = 1024 (512 rows x 2 chunks), block = 128 threads (thread = x)
// chunk 0: q,k (8+8 outputs) + v[0:24) ; chunk 1: v[24:64)
// =====================================================================
__global__ void __launch_bounds__(128) proj_kernel(
                            const float* __restrict__ x,
                            const float* __restrict__ Wq, const float* __restrict__ bq,
                            const float* __restrict__ Wk, const float* __restrict__ bk,
                            const float* __restrict__ Wv, const float* __restrict__ bv)
{
    __shared__ float s_wq[512], s_wk[512], s_wv[4096], s_bq[8], s_bk[8], s_bv[64];
    int tid = threadIdx.x;
    int rid   = blockIdx.x & 511;          // global row = b*128+y
    int chunk = blockIdx.x >> 9;
    int b = rid >> 7, y = rid & 127;

    if (chunk == 0) {
        for (int i = tid; i < 512; i += 128) { s_wq[i] = Wq[i]; s_wk[i] = Wk[i]; }
        for (int i = tid; i < 24*64; i += 128) s_wv[i] = Wv[i];
        if (tid < 8)  { s_bq[tid] = bq[tid]; s_bk[tid] = bk[tid]; }
        if (tid < 24) s_bv[tid] = bv[tid];
    } else {
        for (int i = tid + 24*64; i < 4096; i += 128) s_wv[i] = Wv[i];
        if (tid >= 24 && tid < 64) s_bv[tid] = bv[tid];
    }
    __syncthreads();

    int xcol = tid;
    long pix = ((long)(b*HH + y))*WW + xcol;

    float4 xv[16];
    const float4* xp = (const float4*)(x + pix*64);
#pragma unroll
    for (int c4 = 0; c4 < 16; c4++) xv[c4] = xp[c4];

    if (chunk == 0) {
        int base_qk = (b*CQK)*PLANE + y*WW + xcol;
#pragma unroll 1
        for (int o = 0; o < 8; o++) {
            float aq = s_bq[o], ak = s_bk[o];
            const float4* wq4 = (const float4*)(s_wq + o*64);
            const float4* wk4 = (const float4*)(s_wk + o*64);
#pragma unroll
            for (int c4 = 0; c4 < 16; c4++) {
                float4 wq = wq4[c4], wk = wk4[c4], xc = xv[c4];
                aq += xc.x*wq.x + xc.y*wq.y + xc.z*wq.z + xc.w*wq.w;
                ak += xc.x*wk.x + xc.y*wk.y + xc.z*wk.z + xc.w*wk.w;
            }
            g_q[base_qk + o*PLANE] = aq;
            g_k[base_qk + o*PLANE] = ak;
        }
    }
    int o_lo = (chunk == 0) ? 0 : 24;
    int o_hi = (chunk == 0) ? 24 : 64;
    int base_v = (b*CIN)*PLANE + y*WW + xcol;
#pragma unroll 1
    for (int o = o_lo; o < o_hi; o++) {
        float av = s_bv[o];
        const float4* wv4 = (const float4*)(s_wv + o*64);
#pragma unroll
        for (int c4 = 0; c4 < 16; c4++) {
            float4 wv = wv4[c4], xc = xv[c4];
            av += xc.x*wv.x + xc.y*wv.y + xc.z*wv.z + xc.w*wv.w;
        }
        g_v[base_v + o*PLANE] = av;
    }
}

// =====================================================================
// Kernel B: attention + block-level fold pre-reduction
// block = 8 pixels, 512 threads: warp pair (p) = pixel, half h = n-rows split.
// 2 blocks/SM. smem (floats, total 18912 = 75648 B):
//   s_vp [0,13312): per-pixel v, stride VSTRIDE=1664, m-pair interleaved:
//                   perm(f) = (m>>1)*128 + (m&1)*2 + (cc>>1)*4 + (cc&1)
//                   region REUSED later as chunk[p][1600] flat (AFTER BAR3b!)
//   s_B  [13312,18912) = 5600-float union:
//        phase 1: v halo [64][5][12] @0, q halo @3840, k halo @4320
//        phase 2: s_att [8][25 rows, stride 28] (5600)
//        phase 3: s_partial[5][12][64] (3840)
// =====================================================================
__global__ void __launch_bounds__(ATHREADS, 2) attn_kernel(float* __restrict__ attn_out)
{
    extern __shared__ float sm[];
    float* s_vp  = sm;
    float* s_B   = sm + NPX*VSTRIDE;   // 13312
    float* s_vt  = s_B;
    float* s_qt  = s_B + 3840;
    float* s_kt  = s_B + 4320;
    float* s_att = s_B;          // overlay after halo phase
    float* s_partial = s_B;      // overlay after attn export

    int tid = threadIdx.x;
    int wid = tid >> 5;
    int l   = tid & 31;
    int p   = wid >> 1;          // pixel
    int h   = wid & 1;           // n-row half: h=0 rows 0..12, h=1 rows 13..24
    int b  = blockIdx.x >> 11;
    int r  = blockIdx.x & 2047;
    int y  = r >> 4;
    int x0 = (r & 15) * NPX;

    // ---- P0: stage halo tiles (zero-padded like unfold) ----
    for (int idx = tid; idx < 480; idx += ATHREADS) {
        int c = idx/60, r2 = idx%60, dy = r2/12, xx = r2%12;
        int gy = y + dy - 2, gx = x0 + xx - 2;
        float vq = 0.f, vk = 0.f;
        if (gy >= 0 && gy < HH && gx >= 0 && gx < WW) {
            int gi = ((b*CQK + c)*HH + gy)*WW + gx;
            vq = g_q[gi]; vk = g_k[gi];
        }
        s_qt[idx] = vq; s_kt[idx] = vk;
    }
    for (int idx = tid; idx < 3840; idx += ATHREADS) {
        int ch = idx/60, r2 = idx%60, dy = r2/12, xx = r2%12;
        int gy = y + dy - 2, gx = x0 + xx - 2;
        float vv = 0.f;
        if (gy >= 0 && gy < HH && gx >= 0 && gx < WW)
            vv = g_v[((b*CIN + ch)*HH + gy)*WW + gx];
        s_vt[idx] = vv;
    }
    __syncthreads();   // BAR1

    // ---- P1a: q/k rows -> registers (lane n = row n; both halves load) ----
    float q_reg[8], k_reg[8];
#pragma unroll
    for (int cc = 0; cc < 8; cc++) {
        float vq = 0.f, vk = 0.f;
        if (l < 25) {
            int f  = l*8 + cc;
            int ch = f/25, ko = f - ch*25;
            int off = ch*60 + (ko/5)*12 + (ko%5) + p;
            vq = s_qt[off]; vk = s_kt[off];
        }
        q_reg[cc] = vq; k_reg[cc] = vk;
    }

    // ---- P1b: expand v tile -> per-pixel interleaved vectors ----
    for (int g = tid; g < 1600; g += ATHREADS) {
        int m  = g >> 6, cc = g & 63;
        int ch = g/25,  ko = g - (g/25)*25;
        int off  = ch*60 + (ko/5)*12 + (ko%5);
        int perm = (m>>1)*128 + (m&1)*2 + (cc>>1)*4 + (cc&1);
#pragma unroll
        for (int pp = 0; pp < NPX; pp++) s_vp[pp*VSTRIDE + perm] = s_vt[off + pp];
    }
    __syncthreads();   // BAR2 (halo reads done; s_B reusable)

    // ---- P2: logits + softmax, lane n owns row n (warps redundant; writes split) ----
    {
        float lg[25];
#pragma unroll
        for (int m = 0; m < 25; m++) {
            float acc = 0.f;
#pragma unroll
            for (int cc = 0; cc < 8; cc++)
                acc += q_reg[cc] * __shfl_sync(0xffffffffu, k_reg[cc], m);
            lg[m] = acc;
        }
        int nlo = h*13, nhi = nlo + 13;      // h=0: [0,13)  h=1: [13,26)->caps at 25
        if (l >= nlo && l < nhi && l < 25) {
            float mx = lg[0];
#pragma unroll
            for (int m = 1; m < 25; m++) mx = fmaxf(mx, lg[m]);
            float sum = 0.f;
#pragma unroll
            for (int m = 0; m < 25; m++) { lg[m] = __expf(lg[m] - mx); sum += lg[m]; }
            float inv = 1.0f / sum;
            float* row = s_att + p*APIX + l*ASTRIDE;
#pragma unroll
            for (int m = 0; m < 25; m++) row[m] = lg[m]*inv;
        }
    }
    __syncthreads();   // BAR3

    // ---- P3a: export attn (compact from padded rows, coalesced STG) ----
    long pixb = ((long)(b*HH + y))*WW + x0;
    {
        float* ag = attn_out + pixb*625;
        for (int idx = tid; idx < 5000; idx += ATHREADS) {
            int pp = idx/625, e = idx - pp*625;
            int n = e/25, m = e - n*25;
            ag[idx] = s_att[pp*APIX + n*ASTRIDE + m];
        }
    }

    // ---- P3b: local = attn @ vp; warp half h does rows nbase..nbase+12 ----
    float a0[13], a1[13];
    int nbase = h*13;                    // h=0: 13 rows, h=1: 12 rows
    {
        const float* sa = s_att + p*APIX + nbase*ASTRIDE;
        const float* vl = s_vp + p*VSTRIDE + 4*l;   // lane covers cc = 2l, 2l+1
#pragma unroll
        for (int n = 0; n < 13; n++) { a0[n] = 0.f; a1[n] = 0.f; }
#pragma unroll
        for (int j = 0; j < 6; j++) {               // m = 4j .. 4j+3
            float4 v0 = *(const float4*)(vl + (2*j)*128);
            float4 v1 = *(const float4*)(vl + (2*j+1)*128);
#pragma unroll
            for (int n = 0; n < 13; n++) {
                if (nbase + n < 25) {
                    float4 t = *(const float4*)(sa + n*ASTRIDE + 4*j);  // broadcast LDS.128
                    a0[n] += t.x*v0.x + t.y*v0.z + t.z*v1.x + t.w*v1.z;
                    a1[n] += t.x*v0.y + t.y*v0.w + t.z*v1.y + t.w*v1.w;
                }
            }
        }
        {   // tail m = 24 (block 12 of the interleaved layout)
            float2 v24 = *(const float2*)(vl + 1536);
#pragma unroll
            for (int n = 0; n < 13; n++) {
                if (nbase + n < 25) {
                    float t = sa[n*ASTRIDE + 24];
                    a0[n] += t*v24.x;
                    a1[n] += t*v24.y;
                }
            }
        }
    }
    // BAR3b: ALL v reads done block-wide before any warp overwrites s_vp with
    // its chunk (the sibling warp of the same pixel reads the region this warp
    // writes — without this barrier that is a data race, R13's 3e-2 bug).
    __syncthreads();
    {
        float* ck = s_vp + p*VSTRIDE + nbase*64;
#pragma unroll
        for (int n = 0; n < 13; n++)
            if (nbase + n < 25)
                *(float2*)(ck + n*64 + 2*l) = make_float2(a0[n], a1[n]);
    }
    __syncthreads();   // BAR4 (chunks visible; s_att reads done)

    // ---- P4: in-block fold reduction: chunk -> s_partial[dy][tc][c] ----
    for (int idx = tid; idx < 3840; idx += ATHREADS) {
        int nb  = idx/768;
        int rem = idx - nb*768;
        int tc  = rem >> 6;
        int q   = rem & 63;
        int t   = nb*64 + q;
        int c   = t/5;
        int dy  = t - c*5;
        int f0  = 5*t;
        float acc = 0.f;
#pragma unroll
        for (int j = 0; j < 5; j++) {
            int pw = tc - j;
            if (pw >= 0 && pw < 8) acc += s_vp[pw*VSTRIDE + f0 + j];
        }
        s_partial[dy*768 + tc*64 + c] = acc;
    }
    __syncthreads();   // BAR5

    // ---- P5: write fold partials (coalesced float4) ----
    {
        float4* gp = (float4*)(g_partial + (long)blockIdx.x*3840);
        const float4* ps = (const float4*)s_partial;
        for (int idx = tid; idx < 960; idx += ATHREADS) gp[idx] = ps[idx];
    }
}

// =====================================================================
// Kernel C: final fold = sum of <=10 partials per output + gamma*() + x
// =====================================================================
__global__ void fold_kernel(const float* __restrict__ x,
                            const float* __restrict__ gamma,
                            float* __restrict__ outp)
{
    int tid = threadIdx.x;
    int c  = tid & 63;
    int xi = tid >> 6;
    int b  = blockIdx.x >> 11;
    int r  = blockIdx.x & 2047;
    int Y  = r >> 4;
    int X  = (r & 15)*8 + xi;

    int xp2   = X + 2;
    int xb_hi = xp2 >> 3;          // tc in [0,8)
    int tc_hi = xp2 - (xb_hi<<3);
    int xb_lo = xb_hi - 1;         // tc in [8,12) if tc_hi < 4
    int tc_lo = tc_hi + 8;

    float acc = 0.f;
#pragma unroll
    for (int dy = 0; dy < 5; dy++) {
        int ys = Y + 2 - dy;
        if (ys < 0 || ys >= HH) continue;
        long rowb = ((long)(b*2048 + ys*16))*3840 + dy*768 + c;
        if (xb_hi < 16)
            acc += g_partial[rowb + (long)xb_hi*3840 + tc_hi*64];
        if (xb_lo >= 0 && tc_lo < 12)
            acc += g_partial[rowb + (long)xb_lo*3840 + tc_lo*64];
    }
    long oidx = (((long)(b*HH + Y))*WW + X)*64 + c;
    outp[oidx] = gamma[0]*acc + x[oidx];
}

// =====================================================================
extern "C" void kernel_launch(void* const* d_in, const int* in_sizes, int n_in,
                              void* d_out, int out_size)
{
    const float* x     = (const float*)d_in[0];
    const float* Wq    = (const float*)d_in[1];
    const float* bq    = (const float*)d_in[2];
    const float* Wk    = (const float*)d_in[3];
    const float* bk    = (const float*)d_in[4];
    const float* Wv    = (const float*)d_in[5];
    const float* bv    = (const float*)d_in[6];
    const float* gamma = (const float*)d_in[7];

    float* outp     = (float*)d_out;
    float* attn_out = outp + (long)BATCH*HH*WW*CIN;   // out first, then attn

    cudaFuncSetAttribute(attn_kernel,
                         cudaFuncAttributeMaxDynamicSharedMemorySize, 75648);

    proj_kernel<<<1024, 128>>>(x, Wq, bq, Wk, bk, Wv, bv);
    attn_kernel<<<BATCH*HH*(WW/NPX), ATHREADS, 75648>>>(attn_out);
    fold_kernel<<<BATCH*HH*(WW/NPX), 512>>>(x, gamma, outp);
}

// round 15
// speedup vs baseline: 1.2080x; 1.2080x over previous
#include <cuda_runtime.h>

#define BATCH 4
#define HH 128
#define WW 128
#define CIN 64
#define CQK 8
#define NPX 8          // pixels per attn block (consecutive x)
#define PLANE (HH*WW)
#define VSTRIDE 1664   // per-pixel v region: 13 x 128-float m-pair blocks
#define ASTRIDE 28     // attn row stride (16B-aligned float4 reads)
#define APIX (25*ASTRIDE)   // 700 floats per pixel

// ---------------- scratch (device globals, no runtime alloc) ----------------
__device__ float g_q[BATCH*CQK*PLANE];              //   2 MB
__device__ float g_k[BATCH*CQK*PLANE];              //   2 MB
__device__ float g_v[BATCH*CIN*PLANE];              //  16.8 MB
__device__ float g_partial[(long)BATCH*2048*3840];  // 125.8 MB fold partials

// ---------------- f32x2 packed helpers ----------------
__device__ __forceinline__ unsigned long long dup2(float a) {
    unsigned long long r;
    asm("mov.b64 %0, {%1,%1};" : "=l"(r) : "f"(a));
    return r;
}
__device__ __forceinline__ void fma2(unsigned long long& acc,
                                     unsigned long long a, unsigned long long b) {
    asm("fma.rn.f32x2 %0, %1, %2, %0;" : "+l"(acc) : "l"(a), "l"(b));
}

// =====================================================================
// Kernel A: 1x1-conv projections q,k,v  (NHWC input -> NCHW scratch)
// block = two image rows (256 threads); float4 weight loads  [R12 proven]
// =====================================================================
__global__ void __launch_bounds__(256) proj_kernel(
                            const float* __restrict__ x,
                            const float* __restrict__ Wq, const float* __restrict__ bq,
                            const float* __restrict__ Wk, const float* __restrict__ bk,
                            const float* __restrict__ Wv, const float* __restrict__ bv)
{
    __shared__ float s_wq[512], s_wk[512], s_wv[4096], s_bq[8], s_bk[8], s_bv[64];
    int tid = threadIdx.x;
    for (int i = tid; i < 512; i += 256) { s_wq[i] = Wq[i]; s_wk[i] = Wk[i]; }
    for (int i = tid; i < 4096; i += 256) s_wv[i] = Wv[i];
    if (tid < 8)  { s_bq[tid] = bq[tid]; s_bk[tid] = bk[tid]; }
    if (tid < 64) { s_bv[tid] = bv[tid]; }
    __syncthreads();

    int rowpair = blockIdx.x;            // 0..255
    int b = rowpair >> 6;
    int y = ((rowpair & 63) << 1) | (tid >> 7);
    int xcol = tid & 127;
    long pix = ((long)(b*HH + y))*WW + xcol;

    float4 xv[16];
    const float4* xp = (const float4*)(x + pix*64);
#pragma unroll
    for (int c4 = 0; c4 < 16; c4++) xv[c4] = xp[c4];

    int base_qk = (b*CQK)*PLANE + y*WW + xcol;
#pragma unroll 1
    for (int o = 0; o < 8; o++) {
        float aq = s_bq[o], ak = s_bk[o];
        const float4* wq4 = (const float4*)(s_wq + o*64);
        const float4* wk4 = (const float4*)(s_wk + o*64);
#pragma unroll
        for (int c4 = 0; c4 < 16; c4++) {
            float4 wq = wq4[c4], wk = wk4[c4], xc = xv[c4];
            aq += xc.x*wq.x + xc.y*wq.y + xc.z*wq.z + xc.w*wq.w;
            ak += xc.x*wk.x + xc.y*wk.y + xc.z*wk.z + xc.w*wk.w;
        }
        g_q[base_qk + o*PLANE] = aq;
        g_k[base_qk + o*PLANE] = ak;
    }
    int base_v = (b*CIN)*PLANE + y*WW + xcol;
#pragma unroll 1
    for (int o = 0; o < 64; o++) {
        float av = s_bv[o];
        const float4* wv4 = (const float4*)(s_wv + o*64);
#pragma unroll
        for (int c4 = 0; c4 < 16; c4++) {
            float4 wv = wv4[c4], xc = xv[c4];
            av += xc.x*wv.x + xc.y*wv.y + xc.z*wv.z + xc.w*wv.w;
        }
        g_v[base_v + o*PLANE] = av;
    }
}

// =====================================================================
// Kernel B: attention + block-level fold pre-reduction  [R12 + f32x2 local]
// block = 8 pixels, 256 threads, warp w = pixel w. 3 blocks/SM.
// smem (floats, total 18912 = 75648 B):
//   s_vp [0,13312): per-pixel v, stride VSTRIDE=1664, m-pair interleaved:
//                   perm(f) = (m>>1)*128 + (m&1)*2 + (cc>>1)*4 + (cc&1)
//                   region REUSED later as chunk[p][1600] flat
//   s_B  [13312,18912) = 5600-float union:
//        phase 1: v halo [64][5][12] @0, q halo @3840, k halo @4320
//        phase 2: s_att [8][25 rows, stride 28] (5600)
//        phase 3: s_partial[5][12][64] (3840)
// =====================================================================
__global__ void __launch_bounds__(256, 3) attn_kernel(float* __restrict__ attn_out)
{
    extern __shared__ float sm[];
    float* s_vp  = sm;
    float* s_B   = sm + NPX*VSTRIDE;   // 13312
    float* s_vt  = s_B;
    float* s_qt  = s_B + 3840;
    float* s_kt  = s_B + 4320;
    float* s_att = s_B;          // overlay after halo phase
    float* s_partial = s_B;      // overlay after attn export

    int tid = threadIdx.x;
    int wid = tid >> 5;
    int l   = tid & 31;
    int b  = blockIdx.x >> 11;
    int r  = blockIdx.x & 2047;
    int y  = r >> 4;
    int x0 = (r & 15) * NPX;
    int p  = wid;

    // ---- P0: stage halo tiles (zero-padded like unfold) ----
    for (int idx = tid; idx < 480; idx += 256) {
        int c = idx/60, r2 = idx%60, dy = r2/12, xx = r2%12;
        int gy = y + dy - 2, gx = x0 + xx - 2;
        float vq = 0.f, vk = 0.f;
        if (gy >= 0 && gy < HH && gx >= 0 && gx < WW) {
            int gi = ((b*CQK + c)*HH + gy)*WW + gx;
            vq = g_q[gi]; vk = g_k[gi];
        }
        s_qt[idx] = vq; s_kt[idx] = vk;
    }
    for (int idx = tid; idx < 3840; idx += 256) {
        int ch = idx/60, r2 = idx%60, dy = r2/12, xx = r2%12;
        int gy = y + dy - 2, gx = x0 + xx - 2;
        float vv = 0.f;
        if (gy >= 0 && gy < HH && gx >= 0 && gx < WW)
            vv = g_v[((b*CIN + ch)*HH + gy)*WW + gx];
        s_vt[idx] = vv;
    }
    __syncthreads();   // BAR1

    // ---- P1a: q/k rows -> registers (lane n = row n) ----
    float q_reg[8], k_reg[8];
#pragma unroll
    for (int cc = 0; cc < 8; cc++) {
        float vq = 0.f, vk = 0.f;
        if (l < 25) {
            int f  = l*8 + cc;
            int ch = f/25, ko = f - ch*25;
            int off = ch*60 + (ko/5)*12 + (ko%5) + p;
            vq = s_qt[off]; vk = s_kt[off];
        }
        q_reg[cc] = vq; k_reg[cc] = vk;
    }

    // ---- P1b: expand v tile -> per-pixel interleaved vectors ----
    for (int g = tid; g < 1600; g += 256) {
        int m  = g >> 6, cc = g & 63;
        int ch = g/25,  ko = g - (g/25)*25;
        int off  = ch*60 + (ko/5)*12 + (ko%5);
        int perm = (m>>1)*128 + (m&1)*2 + (cc>>1)*4 + (cc&1);
#pragma unroll
        for (int pp = 0; pp < NPX; pp++) s_vp[pp*VSTRIDE + perm] = s_vt[off + pp];
    }
    __syncthreads();   // BAR2 (halo reads done; s_B reusable)

    // ---- P2: logits + softmax, lane n owns full row n ----
    {
        float lg[25];
#pragma unroll
        for (int m = 0; m < 25; m++) {
            float acc = 0.f;
#pragma unroll
            for (int cc = 0; cc < 8; cc++)
                acc += q_reg[cc] * __shfl_sync(0xffffffffu, k_reg[cc], m);
            lg[m] = acc;
        }
        if (l < 25) {
            float mx = lg[0];
#pragma unroll
            for (int m = 1; m < 25; m++) mx = fmaxf(mx, lg[m]);
            float sum = 0.f;
#pragma unroll
            for (int m = 0; m < 25; m++) { lg[m] = __expf(lg[m] - mx); sum += lg[m]; }
            float inv = 1.0f / sum;
            float* row = s_att + p*APIX + l*ASTRIDE;
#pragma unroll
            for (int m = 0; m < 25; m++) row[m] = lg[m]*inv;
        }
    }
    __syncthreads();   // BAR3

    // ---- P3a: export attn (compact from padded rows, coalesced STG) ----
    long pixb = ((long)(b*HH + y))*WW + x0;
    {
        float* ag = attn_out + pixb*625;
        for (int idx = tid; idx < 5000; idx += 256) {
            int pp = idx/625, e = idx - pp*625;
            int n = e/25, m = e - n*25;
            ag[idx] = s_att[pp*APIX + n*ASTRIDE + m];
        }
    }

    // ---- P3b: local = attn @ vp, quad-m steps, f32x2 packed accumulators ----
    {
        const float* sa = s_att + p*APIX;
        const float* vl = s_vp + p*VSTRIDE + 4*l;   // lane covers cc = 2l, 2l+1
        unsigned long long acc[25];
#pragma unroll
        for (int n = 0; n < 25; n++) acc[n] = 0ull;
#pragma unroll
        for (int j = 0; j < 6; j++) {               // m = 4j .. 4j+3
            const unsigned long long* va = (const unsigned long long*)(vl + (2*j)*128);
            const unsigned long long* vb = (const unsigned long long*)(vl + (2*j+1)*128);
            unsigned long long v01 = va[0];   // (m=4j  : c0,c1)
            unsigned long long v23 = va[1];   // (m=4j+1: c0,c1)
            unsigned long long v45 = vb[0];   // (m=4j+2: c0,c1)
            unsigned long long v67 = vb[1];   // (m=4j+3: c0,c1)
#pragma unroll
            for (int n = 0; n < 25; n++) {
                float4 t = *(const float4*)(sa + n*ASTRIDE + 4*j);  // broadcast LDS.128
                fma2(acc[n], dup2(t.x), v01);
                fma2(acc[n], dup2(t.y), v23);
                fma2(acc[n], dup2(t.z), v45);
                fma2(acc[n], dup2(t.w), v67);
            }
        }
        {   // tail m = 24 (block 12 of the interleaved layout)
            unsigned long long v24 = *(const unsigned long long*)(vl + 1536);
#pragma unroll
            for (int n = 0; n < 25; n++)
                fma2(acc[n], dup2(sa[n*ASTRIDE + 24]), v24);
        }
        // store chunk (flat layout f = n*64+cc) over own s_vp region
        float* ck = s_vp + p*VSTRIDE;
#pragma unroll
        for (int n = 0; n < 25; n++)
            *(unsigned long long*)(ck + n*64 + 2*l) = acc[n];
    }
    __syncthreads();   // BAR4 (chunks visible; s_att reads done)

    // ---- P4: in-block fold reduction: chunk -> s_partial[dy][tc][c] ----
    for (int idx = tid; idx < 3840; idx += 256) {
        int nb  = idx/768;
        int rem = idx - nb*768;
        int tc  = rem >> 6;
        int q   = rem & 63;
        int t   = nb*64 + q;
        int c   = t/5;
        int dy  = t - c*5;
        int f0  = 5*t;
        float acc = 0.f;
#pragma unroll
        for (int j = 0; j < 5; j++) {
            int pw = tc - j;
            if (pw >= 0 && pw < 8) acc += s_vp[pw*VSTRIDE + f0 + j];
        }
        s_partial[dy*768 + tc*64 + c] = acc;
    }
    __syncthreads();   // BAR5

    // ---- P5: write fold partials (coalesced float4) ----
    {
        float4* gp = (float4*)(g_partial + (long)blockIdx.x*3840);
        const float4* ps = (const float4*)s_partial;
        for (int idx = tid; idx < 960; idx += 256) gp[idx] = ps[idx];
    }
}

// =====================================================================
// Kernel C: final fold = sum of <=10 partials per output + gamma*() + x
// =====================================================================
__global__ void fold_kernel(const float* __restrict__ x,
                            const float* __restrict__ gamma,
                            float* __restrict__ outp)
{
    int tid = threadIdx.x;
    int c  = tid & 63;
    int xi = tid >> 6;
    int b  = blockIdx.x >> 11;
    int r  = blockIdx.x & 2047;
    int Y  = r >> 4;
    int X  = (r & 15)*8 + xi;

    int xp2   = X + 2;
    int xb_hi = xp2 >> 3;          // tc in [0,8)
    int tc_hi = xp2 - (xb_hi<<3);
    int xb_lo = xb_hi - 1;         // tc in [8,12) if tc_hi < 4
    int tc_lo = tc_hi + 8;

    float acc = 0.f;
#pragma unroll
    for (int dy = 0; dy < 5; dy++) {
        int ys = Y + 2 - dy;
        if (ys < 0 || ys >= HH) continue;
        long rowb = ((long)(b*2048 + ys*16))*3840 + dy*768 + c;
        if (xb_hi < 16)
            acc += g_partial[rowb + (long)xb_hi*3840 + tc_hi*64];
        if (xb_lo >= 0 && tc_lo < 12)
            acc += g_partial[rowb + (long)xb_lo*3840 + tc_lo*64];
    }
    long oidx = (((long)(b*HH + Y))*WW + X)*64 + c;
    outp[oidx] = gamma[0]*acc + x[oidx];
}

// =====================================================================
extern "C" void kernel_launch(void* const* d_in, const int* in_sizes, int n_in,
                              void* d_out, int out_size)
{
    const float* x     = (const float*)d_in[0];
    const float* Wq    = (const float*)d_in[1];
    const float* bq    = (const float*)d_in[2];
    const float* Wk    = (const float*)d_in[3];
    const float* bk    = (const float*)d_in[4];
    const float* Wv    = (const float*)d_in[5];
    const float* bv    = (const float*)d_in[6];
    const float* gamma = (const float*)d_in[7];

    float* outp     = (float*)d_out;
    float* attn_out = outp + (long)BATCH*HH*WW*CIN;   // out first, then attn

    cudaFuncSetAttribute(attn_kernel,
                         cudaFuncAttributeMaxDynamicSharedMemorySize, 75648);

    proj_kernel<<<BATCH*HH/2, 256>>>(x, Wq, bq, Wk, bk, Wv, bv);
    attn_kernel<<<BATCH*HH*(WW/NPX), 256, 75648>>>(attn_out);
    fold_kernel<<<BATCH*HH*(WW/NPX), 512>>>(x, gamma, outp);
}